// round 2
// baseline (speedup 1.0000x reference)
#include <cuda_runtime.h>
#include <math.h>

#define NB 128
#define NK 64
#define NM 2048
#define NAD 128
#define NQD 128
#define NH 256
#define NC 32
#define HS 72      // padded row stride for transposed h tiles
#define TM 64      // points per CTA

// ---- scratch (no allocation allowed) ----
__device__ float d_inv[NB*NK];
__device__ float d_c[NM];
__device__ float d_P[NB*NH];       // pm_W1[:, :256] @ global_s + pm_b1
__device__ float d_Qc[NM*NH];      // pm_W1[:, 256:384] @ query[m]
__device__ float d_W2T[NH*NH];     // pm_W2 transposed (k-major)
__device__ float d_W3T[NH*NH];     // pm_W3 transposed (k-major)
__device__ float d_weff[NQD+1];    // qW^T kW, and qb.kW at [128]

__device__ __forceinline__ float gelu_f(float x){
    return 0.5f*x*(1.0f + erff(x*0.7071067811865475f));
}

// ---------------- prep: w_eff = qW^T kW, b_eff = qb.kW ----------------
__global__ void k_weff(const float* __restrict__ qW, const float* __restrict__ qb,
                       const float* __restrict__ kW){
    int t = threadIdx.x;  // 0..127
    float acc = 0.f;
    #pragma unroll 8
    for (int a=0;a<NAD;a++) acc += qW[a*NQD+t]*kW[a];
    d_weff[t] = acc;
    if (t==0){
        float be = 0.f;
        for (int a=0;a<NAD;a++) be += qb[a]*kW[a];
        d_weff[NQD] = be;
    }
}

// ---------------- prep: transpose pm_W2 / pm_W3 to k-major ----------------
__global__ void k_transpose(const float* __restrict__ W2, const float* __restrict__ W3){
    int idx = blockIdx.x*256 + threadIdx.x;          // 0..65535
    const float* src = blockIdx.y ? W3 : W2;
    float* dst = blockIdx.y ? d_W3T : d_W2T;
    int k = idx >> 8, j = idx & 255;
    dst[idx] = src[j*NH + k];
}

// ---------------- prep per-batch: inv, global MLP, P ----------------
__global__ void k_prep_b(const float* __restrict__ g,
                         const float* __restrict__ gW1, const float* __restrict__ gb1,
                         const float* __restrict__ gW2, const float* __restrict__ gb2,
                         const float* __restrict__ gW3, const float* __restrict__ gb3,
                         const float* __restrict__ pW1, const float* __restrict__ pb1){
    __shared__ float inv_s[NK];
    __shared__ float h1[NH];
    __shared__ float h2[NH];
    __shared__ float h3[NH];
    int b = blockIdx.x, t = threadIdx.x;  // 256 threads
    if (t < NK){
        const float* gp = g + ((size_t)b*NK + t)*3;
        float v = sqrtf(gp[0]*gp[0] + gp[1]*gp[1] + gp[2]*gp[2]);
        inv_s[t] = v;
        d_inv[b*NK + t] = v;
    }
    __syncthreads();
    {
        float acc = gb1[t];
        const float* w = gW1 + t*NK;
        #pragma unroll 8
        for (int k=0;k<NK;k++) acc += w[k]*inv_s[k];
        h1[t] = gelu_f(acc);
    }
    __syncthreads();
    {
        float acc = gb2[t];
        const float* w = gW2 + t*NH;
        #pragma unroll 8
        for (int k=0;k<NH;k++) acc += w[k]*h1[k];
        h2[t] = gelu_f(acc);
    }
    __syncthreads();
    {
        float acc = gb3[t];
        const float* w = gW3 + t*NH;
        #pragma unroll 8
        for (int k=0;k<NH;k++) acc += w[k]*h2[k];
        h3[t] = acc;                          // no activation on layer 3
    }
    __syncthreads();
    {
        float acc = pb1[t];                   // fold pm_b1 into P
        const float* w = pW1 + (size_t)t*385; // cols [0:256) act on global_s
        #pragma unroll 8
        for (int k=0;k<NH;k++) acc += w[k]*h3[k];
        d_P[b*NH + t] = acc;
    }
}

// ---------------- prep per-query: c[m], Qc[m][:] ----------------
__global__ void k_prep_m(const float* __restrict__ query, const float* __restrict__ pW1){
    __shared__ float q_s[NQD];
    int m = blockIdx.x, t = threadIdx.x;      // 256 threads
    if (t < NQD) q_s[t] = query[m*NQD + t];
    __syncthreads();
    {
        float acc = 0.f;
        const float* w = pW1 + (size_t)t*385 + NH;  // cols [256:384) act on query
        #pragma unroll 8
        for (int q=0;q<NQD;q++) acc += w[q]*q_s[q];
        d_Qc[(size_t)m*NH + t] = acc;
    }
    if (t == 0){
        float c = d_weff[NQD];
        for (int q=0;q<NQD;q++) c += q_s[q]*d_weff[q];
        d_c[m] = c * 0.08838834764831845f;    // 1/sqrt(128)
    }
}

// ---------------- fused main: attention + layer1 + GEMM x2 + heads ----------------
template<bool GELU>
__device__ __forceinline__ void gemm_layer(const float* hIn, float* wt,
                                           const float* __restrict__ WT,
                                           const float* __restrict__ bias,
                                           float* hOut, int tid){
    int tx = tid & 31;   // 32 col-groups x 8 cols = 256 cols (output neurons)
    int ty = tid >> 5;   // 8 row-groups x 8 rows = 64 points
    float acc[8][8];
    #pragma unroll
    for (int i=0;i<8;i++)
        #pragma unroll
        for (int j=0;j<8;j++) acc[i][j] = 0.f;

    for (int kk=0; kk<NH; kk+=8){
        __syncthreads();                       // protect previous tile reads
        const float4* src = (const float4*)(WT + kk*NH);
        float4* dst = (float4*)wt;
        dst[tid*2+0] = src[tid*2+0];
        dst[tid*2+1] = src[tid*2+1];
        __syncthreads();
        #pragma unroll
        for (int t=0;t<8;t++){
            const float* arow = hIn + (kk+t)*HS + ty*8;   // broadcast within warp
            const float* brow = wt + t*NH + tx*8;         // conflict-free float4
            float4 a0 = *(const float4*)(arow);
            float4 a1 = *(const float4*)(arow+4);
            float4 b0 = *(const float4*)(brow);
            float4 b1 = *(const float4*)(brow+4);
            float a[8]  = {a0.x,a0.y,a0.z,a0.w,a1.x,a1.y,a1.z,a1.w};
            float bb[8] = {b0.x,b0.y,b0.z,b0.w,b1.x,b1.y,b1.z,b1.w};
            #pragma unroll
            for (int i=0;i<8;i++)
                #pragma unroll
                for (int j=0;j<8;j++) acc[i][j] = fmaf(a[i], bb[j], acc[i][j]);
        }
    }
    __syncthreads();
    #pragma unroll
    for (int j=0;j<8;j++){
        int col = tx*8 + j;
        float bv = bias[col];
        float* orow = hOut + col*HS + ty*8;
        float tmp[8];
        #pragma unroll
        for (int i=0;i<8;i++){
            float v = acc[i][j] + bv;
            tmp[i] = GELU ? gelu_f(v) : v;
        }
        *(float4*)(orow)   = make_float4(tmp[0],tmp[1],tmp[2],tmp[3]);
        *(float4*)(orow+4) = make_float4(tmp[4],tmp[5],tmp[6],tmp[7]);
    }
    __syncthreads();
}

__global__ void __launch_bounds__(256, 1)
k_main(const float* __restrict__ g, const float* __restrict__ pW1,
       const float* __restrict__ pb2, const float* __restrict__ pb3,
       const float* __restrict__ tW, const float* __restrict__ tb,
       const float* __restrict__ wW, const float* __restrict__ wb,
       const float* __restrict__ cW, const float* __restrict__ cb,
       float* __restrict__ out){
    extern __shared__ float sm[];
    float* hA     = sm;                 // [256][HS]
    float* hB     = hA + NH*HS;         // [256][HS]
    float* wt     = hB + NH*HS;         // [8][256]
    float* inv_s  = wt + 8*NH;          // [64]
    float* ainv_s = inv_s + 64;         // [64]
    float* y0_s   = ainv_s + 64;        // [64][3]
    float* g_s    = y0_s + 192;         // [64][3]
    float* P_s    = g_s + 192;          // [256]
    float* w1c_s  = P_s + 256;          // [256]

    int tid = threadIdx.x;
    int b = blockIdx.y;
    int m0 = blockIdx.x * TM;

    if (tid < 64)                 inv_s[tid]    = d_inv[b*NK + tid];
    if (tid >= 64 && tid < 256)   g_s[tid-64]   = g[(size_t)b*NK*3 + (tid-64)];
    P_s[tid]   = d_P[b*NH + tid];
    w1c_s[tid] = pW1[(size_t)tid*385 + 384];   // ainv column
    __syncthreads();

    // ---- attention (threads 0..63, one point each) ----
    if (tid < TM){
        float cm = d_c[m0 + tid];
        float mx = -1e30f;
        #pragma unroll 8
        for (int k=0;k<NK;k++) mx = fmaxf(mx, cm*inv_s[k]);
        float sum=0.f, y0=0.f, y1=0.f, y2=0.f, ai=0.f;
        #pragma unroll 4
        for (int k=0;k<NK;k++){
            float e = expf(cm*inv_s[k] - mx);
            sum += e;
            y0 += e*g_s[k*3+0]; y1 += e*g_s[k*3+1]; y2 += e*g_s[k*3+2];
            ai += e*inv_s[k];
        }
        float r = 1.f/sum;
        y0_s[tid*3+0]=y0*r; y0_s[tid*3+1]=y1*r; y0_s[tid*3+2]=y2*r;
        ainv_s[tid] = ai*r;
    }
    __syncthreads();

    // ---- layer 1 (separable): hA[j][p] = gelu(P[j] + Qc[m][j] + w1c[j]*ainv[p]) ----
    {
        float Pv = P_s[tid], wc = w1c_s[tid];
        const float* qc = d_Qc + (size_t)m0*NH + tid;
        float* row = hA + tid*HS;
        #pragma unroll 4
        for (int p=0;p<TM;p++){
            float v = Pv + qc[(size_t)p*NH] + wc*ainv_s[p];
            row[p] = gelu_f(v);
        }
    }
    __syncthreads();

    // ---- layer 2: hB = gelu(hA @ W2^T + b2), layer 3: hA = hB @ W3^T + b3 ----
    gemm_layer<true >(hA, wt, d_W2T, pb2, hB, tid);
    gemm_layer<false>(hB, wt, d_W3T, pb3, hA, tid);   // s now in hA[j][p]

    // ---- heads ----
    float* outY = out;
    float* outT = out + (size_t)NB*NM*3;
    float* outW = out + (size_t)NB*NM*3 + (size_t)NB*NM*NC;
    size_t base = (size_t)b*NM + m0;
    const float* sA = hA;
    for (int task = tid; task < TM*34; task += 256){
        int p = task / 34;
        int o = task - p*34;
        const float* wrow; float bv;
        if      (o < 32){ wrow = tW + o*NH; bv = tb[o]; }
        else if (o == 32){ wrow = wW;       bv = wb[0]; }
        else             { wrow = cW;       bv = cb[0]; }
        float acc = bv;
        #pragma unroll 8
        for (int j=0;j<NH;j++) acc += sA[j*HS + p]*wrow[j];
        size_t pi = base + p;
        if      (o < 32) outT[pi*NC + o] = acc;
        else if (o == 32) outW[pi] = acc;
        else {
            float gate = 1.f/(1.f + expf(-acc));   // sigmoid; clip(0,1) is no-op
            outY[pi*3+0] = y0_s[p*3+0]*gate;
            outY[pi*3+1] = y0_s[p*3+1]*gate;
            outY[pi*3+2] = y0_s[p*3+2]*gate;
        }
    }
}

// ---------------- launch ----------------
extern "C" void kernel_launch(void* const* d_in, const int* in_sizes, int n_in,
                              void* d_out, int out_size){
    const float* g    = (const float*)d_in[0];
    const float* query= (const float*)d_in[1];
    const float* qW   = (const float*)d_in[2];
    const float* qb   = (const float*)d_in[3];
    const float* kW   = (const float*)d_in[4];
    // d_in[5] = kb: cancels in softmax (constant over k), provably unused
    const float* gW1  = (const float*)d_in[6];
    const float* gb1  = (const float*)d_in[7];
    const float* gW2  = (const float*)d_in[8];
    const float* gb2  = (const float*)d_in[9];
    const float* gW3  = (const float*)d_in[10];
    const float* gb3  = (const float*)d_in[11];
    const float* pW1  = (const float*)d_in[12];
    const float* pb1  = (const float*)d_in[13];
    const float* pW2  = (const float*)d_in[14];
    const float* pb2  = (const float*)d_in[15];
    const float* pW3  = (const float*)d_in[16];
    const float* pb3  = (const float*)d_in[17];
    const float* tW   = (const float*)d_in[18];
    const float* tb   = (const float*)d_in[19];
    const float* wW   = (const float*)d_in[20];
    const float* wb   = (const float*)d_in[21];
    const float* cW   = (const float*)d_in[22];
    const float* cb   = (const float*)d_in[23];
    float* out = (float*)d_out;

    const int SMEM_MAIN = (2*NH*HS + 8*NH + 64 + 64 + 192 + 192 + 256 + 256) * 4;
    cudaFuncSetAttribute(k_main, cudaFuncAttributeMaxDynamicSharedMemorySize, SMEM_MAIN);

    k_weff<<<1, 128>>>(qW, qb, kW);
    k_transpose<<<dim3(256, 2), 256>>>(pW2, pW3);
    k_prep_b<<<NB, 256>>>(g, gW1, gb1, gW2, gb2, gW3, gb3, pW1, pb1);
    k_prep_m<<<NM, 256>>>(query, pW1);
    k_main<<<dim3(NM/TM, NB), 256, SMEM_MAIN>>>(g, pW1, pb2, pb3,
                                                tW, tb, wW, wb, cW, cb, out);
}

// round 7
// speedup vs baseline: 8.6438x; 8.6438x over previous
#include <cuda_runtime.h>
#include <math.h>

#define NB 128
#define NK 64
#define NM 2048
#define NQD 128
#define NH 256
#define NC 32
#define HS 68      // padded row stride (mod 32 = 4 -> low smem conflicts), 16B aligned
#define TM 64      // points per CTA
#define KT 16      // k-tile for weight staging

// ---- scratch (no allocation allowed) ----
__device__ float d_inv[NB*NK];
__device__ float d_P[NB*NH];       // pm_W1[:, :256] @ global_s + pm_b1
__device__ float d_Qc[NM*NH];      // pm_W1[:, 256:384] @ query[m]
__device__ float d_W2T[NH*NH];     // pm_W2 transposed (k-major)
__device__ float d_W3T[NH*NH];     // pm_W3 transposed (k-major)
__device__ float d_weff[NQD+1];    // qW^T kW, and qb.kW at [128]

__device__ __forceinline__ float gelu_f(float x){
    return 0.5f*x*(1.0f + erff(x*0.7071067811865475f));
}

__device__ __forceinline__ float warp_red_sum(float v){
    v += __shfl_xor_sync(0xffffffffu, v, 16);
    v += __shfl_xor_sync(0xffffffffu, v, 8);
    v += __shfl_xor_sync(0xffffffffu, v, 4);
    v += __shfl_xor_sync(0xffffffffu, v, 2);
    v += __shfl_xor_sync(0xffffffffu, v, 1);
    return v;
}
__device__ __forceinline__ float warp_red_max(float v){
    v = fmaxf(v, __shfl_xor_sync(0xffffffffu, v, 16));
    v = fmaxf(v, __shfl_xor_sync(0xffffffffu, v, 8));
    v = fmaxf(v, __shfl_xor_sync(0xffffffffu, v, 4));
    v = fmaxf(v, __shfl_xor_sync(0xffffffffu, v, 2));
    v = fmaxf(v, __shfl_xor_sync(0xffffffffu, v, 1));
    return v;
}

// ================= unified prep kernel (roles by blockIdx.x) =================
// [0,128)   : transpose pm_W2 -> d_W2T
// [128,256) : transpose pm_W3 -> d_W3T
// [256,384) : per-batch: inv, global MLP, P
// 384       : weff = qW^T kW, beff = qb.kW
// [385,1409): Qc (2 queries per block, warp-cooperative, coalesced)
__global__ void __launch_bounds__(512,1) k_prep(
    const float* __restrict__ g, const float* __restrict__ query,
    const float* __restrict__ qW, const float* __restrict__ qb,
    const float* __restrict__ kW,
    const float* __restrict__ gW1, const float* __restrict__ gb1,
    const float* __restrict__ gW2, const float* __restrict__ gb2,
    const float* __restrict__ gW3, const float* __restrict__ gb3,
    const float* __restrict__ pW1, const float* __restrict__ pb1,
    const float* __restrict__ pW2, const float* __restrict__ pW3)
{
    __shared__ float sb[1088];
    int blk = blockIdx.x, tid = threadIdx.x;

    if (blk < 128){
        int idx = blk*512 + tid;
        d_W2T[idx] = pW2[(idx & 255)*NH + (idx >> 8)];
    } else if (blk < 256){
        int idx = (blk-128)*512 + tid;
        d_W3T[idx] = pW3[(idx & 255)*NH + (idx >> 8)];
    } else if (blk < 384){
        int b = blk - 256;
        float* inv_s = sb;          // 64
        float* h1 = sb + 64;        // 256
        float* h2 = sb + 320;       // 256
        float* h3 = sb + 576;       // 256
        if (tid < NK){
            const float* gp = g + ((size_t)b*NK + tid)*3;
            float v = sqrtf(gp[0]*gp[0] + gp[1]*gp[1] + gp[2]*gp[2]);
            inv_s[tid] = v;
            d_inv[b*NK + tid] = v;
        }
        __syncthreads();
        if (tid < NH){
            float acc = gb1[tid];
            const float* wr = gW1 + tid*NK;
            #pragma unroll 8
            for (int k=0;k<NK;k++) acc += wr[k]*inv_s[k];
            h1[tid] = gelu_f(acc);
        }
        __syncthreads();
        if (tid < NH){
            float acc = gb2[tid];
            const float* wr = gW2 + tid*NH;
            #pragma unroll 8
            for (int k=0;k<NH;k++) acc += wr[k]*h1[k];
            h2[tid] = gelu_f(acc);
        }
        __syncthreads();
        if (tid < NH){
            float acc = gb3[tid];
            const float* wr = gW3 + tid*NH;
            #pragma unroll 8
            for (int k=0;k<NH;k++) acc += wr[k]*h2[k];
            h3[tid] = acc;
        }
        __syncthreads();
        if (tid < NH){
            float acc = pb1[tid];
            const float* wr = pW1 + (size_t)tid*385;   // cols [0:256) act on global_s
            #pragma unroll 8
            for (int k=0;k<NH;k++) acc += wr[k]*h3[k];
            d_P[b*NH + tid] = acc;
        }
    } else if (blk == 384){
        if (tid < NQD){
            float acc = 0.f;
            #pragma unroll 8
            for (int a=0;a<NQD;a++) acc += qW[a*NQD+tid]*kW[a];
            d_weff[tid] = acc;
        }
        if (tid == 128){
            float be = 0.f;
            for (int a=0;a<NQD;a++) be += qb[a]*kW[a];
            d_weff[NQD] = be;
        }
    } else {
        int bq = blk - 385;                 // 0..1023, handles m = 2bq, 2bq+1
        float* q_s = sb;                    // [2][128]
        if (tid < 256)
            q_s[tid] = query[((size_t)bq*2 + (tid>>7))*NQD + (tid & 127)];
        __syncthreads();
        int h = tid >> 8;                   // which m
        int wv = (tid >> 5) & 7;            // warp within half
        int lid = tid & 31;
        int m = bq*2 + h;
        const float* qs = q_s + h*128;
        for (int it=0; it<32; it++){
            int j = it*8 + wv;
            const float* row = pW1 + (size_t)j*385 + NH;   // cols [256:384)
            float acc = row[lid]      * qs[lid]
                      + row[lid+32]   * qs[lid+32]
                      + row[lid+64]   * qs[lid+64]
                      + row[lid+96]   * qs[lid+96];
            acc = warp_red_sum(acc);
            if (lid == 0) d_Qc[(size_t)m*NH + j] = acc;
        }
    }
}

// ================= GEMM layer: 64 pts x 256 outs x 256 k =====================
// 512 threads. tx owns cols {tx*4..tx*4+3, 128+tx*4..+3}; ty owns 4 rows.
// Register-prefetch double-buffered weight staging, 1 barrier per k-tile.
template<bool GELU>
__device__ __forceinline__ void gemm_layer(const float* __restrict__ hIn,
        float* __restrict__ wt, const float* __restrict__ WT,
        const float* __restrict__ bias, float* __restrict__ hOut, int tid){
    const int tx  = tid & 31;
    const int ty4 = (tid >> 5) << 2;
    float acc[4][8];
    #pragma unroll
    for (int i=0;i<4;i++)
        #pragma unroll
        for (int j=0;j<8;j++) acc[i][j] = 0.f;

    {   // preload tile 0
        const float4* s = (const float4*)WT;
        float4* d = (float4*)wt;
        d[tid*2]   = s[tid*2];
        d[tid*2+1] = s[tid*2+1];
    }
    __syncthreads();

    for (int kt=0; kt<NH/KT; kt++){
        float4 r0, r1;
        if (kt < NH/KT-1){
            const float4* s = (const float4*)(WT + (kt+1)*KT*NH);
            r0 = s[tid*2]; r1 = s[tid*2+1];
        }
        const float* buf = wt + (kt & 1)*(KT*NH);
        #pragma unroll
        for (int t=0;t<KT;t++){
            float4 av = *(const float4*)(hIn + (kt*KT+t)*HS + ty4);      // broadcast
            float4 b0 = *(const float4*)(buf + t*NH + tx*4);             // conflict-free
            float4 b1 = *(const float4*)(buf + t*NH + 128 + tx*4);       // conflict-free
            float a[4]  = {av.x,av.y,av.z,av.w};
            float bb[8] = {b0.x,b0.y,b0.z,b0.w,b1.x,b1.y,b1.z,b1.w};
            #pragma unroll
            for (int i=0;i<4;i++)
                #pragma unroll
                for (int j=0;j<8;j++) acc[i][j] = fmaf(a[i], bb[j], acc[i][j]);
        }
        if (kt < NH/KT-1){
            float4* d = (float4*)(wt + ((kt+1) & 1)*(KT*NH));
            d[tid*2]   = r0;
            d[tid*2+1] = r1;
        }
        __syncthreads();
    }

    #pragma unroll
    for (int j=0;j<8;j++){
        int col = (j < 4) ? (tx*4 + j) : (128 + tx*4 + (j-4));
        float bv = bias[col];
        float v0 = acc[0][j]+bv, v1 = acc[1][j]+bv, v2 = acc[2][j]+bv, v3 = acc[3][j]+bv;
        if (GELU){ v0 = gelu_f(v0); v1 = gelu_f(v1); v2 = gelu_f(v2); v3 = gelu_f(v3); }
        *(float4*)(hOut + col*HS + ty4) = make_float4(v0,v1,v2,v3);
    }
    __syncthreads();
}

// ================= fused main =================
__global__ void __launch_bounds__(512, 1)
k_main(const float* __restrict__ g, const float* __restrict__ query,
       const float* __restrict__ pW1,
       const float* __restrict__ pb2, const float* __restrict__ pb3,
       const float* __restrict__ tW, const float* __restrict__ tb,
       const float* __restrict__ wW, const float* __restrict__ wb,
       const float* __restrict__ cW, const float* __restrict__ cb,
       float* __restrict__ out){
    extern __shared__ float sm[];
    float* hA     = sm;                   // [256][HS]
    float* hB     = hA + NH*HS;           // [256][HS]  (also head-weight stage)
    float* wt     = hB + NH*HS;           // [2][KT*NH]
    float* inv_s  = wt + 2*KT*NH;         // 64
    float* ainv_s = inv_s + 64;           // 64
    float* y0_s   = ainv_s + 64;          // 192
    float* g_s    = y0_s + 192;           // 192
    float* P_s    = g_s + 192;            // 256
    float* w1c_s  = P_s + 256;            // 256
    float* c_s    = w1c_s + 256;          // 64
    float* weff_s = c_s + 64;             // 132

    int tid = threadIdx.x;
    int b = blockIdx.y;
    int m0 = blockIdx.x * TM;
    int lid = tid & 31, w = tid >> 5;     // 16 warps

    if (tid < 64)                 inv_s[tid]  = d_inv[b*NK + tid];
    if (tid >= 64 && tid < 256)   g_s[tid-64] = g[(size_t)b*NK*3 + (tid-64)];
    if (tid < 256){
        P_s[tid]   = d_P[b*NH + tid];
        w1c_s[tid] = pW1[(size_t)tid*385 + 384];   // ainv column
    }
    if (tid < NQD+1) weff_s[tid] = d_weff[tid];
    __syncthreads();

    // ---- c[p] = (query[m0+p].weff + beff)/sqrt(128): 4 points per warp ----
    #pragma unroll
    for (int i=0;i<4;i++){
        int p = w*4 + i;
        const float* q = query + (size_t)(m0+p)*NQD;
        float acc = q[lid]      * weff_s[lid]
                  + q[lid+32]   * weff_s[lid+32]
                  + q[lid+64]   * weff_s[lid+64]
                  + q[lid+96]   * weff_s[lid+96];
        acc = warp_red_sum(acc);
        if (lid == 0) c_s[p] = (acc + weff_s[NQD]) * 0.08838834764831845f;
    }
    __syncthreads();

    // ---- attention: warp-cooperative softmax over K=64, 4 points per warp ----
    {
        float i1 = inv_s[lid], i2 = inv_s[lid+32];
        float gx0 = g_s[lid*3],      gx1 = g_s[lid*3+1],      gx2 = g_s[lid*3+2];
        float gy0 = g_s[(lid+32)*3], gy1 = g_s[(lid+32)*3+1], gy2 = g_s[(lid+32)*3+2];
        #pragma unroll
        for (int i=0;i<4;i++){
            int p = w*4 + i;
            float cm = c_s[p];
            float t1 = cm*i1, t2 = cm*i2;
            float mx = warp_red_max(fmaxf(t1, t2));
            float e1 = expf(t1 - mx), e2 = expf(t2 - mx);
            float s  = warp_red_sum(e1 + e2);
            float a0 = warp_red_sum(e1*gx0 + e2*gy0);
            float a1 = warp_red_sum(e1*gx1 + e2*gy1);
            float a2 = warp_red_sum(e1*gx2 + e2*gy2);
            float ai = warp_red_sum(e1*i1 + e2*i2);
            if (lid == 0){
                float r = 1.f/s;
                y0_s[p*3+0] = a0*r; y0_s[p*3+1] = a1*r; y0_s[p*3+2] = a2*r;
                ainv_s[p] = ai*r;
            }
        }
    }
    __syncthreads();

    // ---- layer 1 (separable): hA[j][p] = gelu(P[j] + Qc[m][j] + w1c[j]*ainv[p]) ----
    {
        int j = tid & 255, h = tid >> 8, p0 = h*32;
        float Pv = P_s[j], wc = w1c_s[j];
        const float* qc = d_Qc + (size_t)(m0+p0)*NH + j;   // coalesced across j
        float* row = hA + j*HS + p0;
        #pragma unroll 4
        for (int p=0;p<32;p++)
            row[p] = gelu_f(Pv + qc[(size_t)p*NH] + wc*ainv_s[p0+p]);
    }
    __syncthreads();

    // ---- layer 2 + layer 3 ----
    gemm_layer<true >(hA, wt, d_W2T, pb2, hB, tid);
    gemm_layer<false>(hB, wt, d_W3T, pb3, hA, tid);    // s in hA[j][p]

    // ---- stage head weights transposed into hB: hw[j*40 + o], o<34 ----
    for (int idx = tid; idx < 34*NH; idx += 512){
        int o = idx >> 8, j = idx & 255;
        float v = (o < 32) ? tW[o*NH + j] : ((o == 32) ? wW[j] : cW[j]);
        hB[j*40 + o] = v;
    }
    __syncthreads();

    // ---- heads: lanes own outputs (conflict-free), ty owns 4 points ----
    {
        int tx = lid;           // output o = tx (plus o = 32+tx for tx<2)
        int p0 = w * 4;         // hmm: w is 0..15 -> p0 covers 0..60
        float acc0[4] = {0.f,0.f,0.f,0.f};
        float acc1[4] = {0.f,0.f,0.f,0.f};
        #pragma unroll 4
        for (int j=0;j<NH;j++){
            float4 a = *(const float4*)(hA + j*HS + p0);   // warp broadcast
            float w0 = hB[j*40 + tx];                      // lane-stride-1
            float w1 = hB[j*40 + 32 + tx];                 // valid data only for tx<2
            acc0[0] = fmaf(a.x, w0, acc0[0]);
            acc0[1] = fmaf(a.y, w0, acc0[1]);
            acc0[2] = fmaf(a.z, w0, acc0[2]);
            acc0[3] = fmaf(a.w, w0, acc0[3]);
            acc1[0] = fmaf(a.x, w1, acc1[0]);
            acc1[1] = fmaf(a.y, w1, acc1[1]);
            acc1[2] = fmaf(a.z, w1, acc1[2]);
            acc1[3] = fmaf(a.w, w1, acc1[3]);
        }
        size_t base = (size_t)b*NM + m0;
        float* outT = out + (size_t)NB*NM*3;
        float bv = tb[tx];
        #pragma unroll
        for (int i=0;i<4;i++)
            outT[(base + p0 + i)*NC + tx] = acc0[i] + bv;   // coalesced
        if (tx == 0){
            float* outW = out + (size_t)NB*NM*3 + (size_t)NB*NM*NC;
            float wbv = wb[0];
            #pragma unroll
            for (int i=0;i<4;i++) outW[base + p0 + i] = acc1[i] + wbv;
        }
        if (tx == 1){
            float cbv = cb[0];
            #pragma unroll
            for (int i=0;i<4;i++){
                int p = p0 + i;
                float gate = 1.f/(1.f + expf(-(acc1[i] + cbv)));
                size_t pi = base + p;
                out[pi*3+0] = y0_s[p*3+0]*gate;
                out[pi*3+1] = y0_s[p*3+1]*gate;
                out[pi*3+2] = y0_s[p*3+2]*gate;
            }
        }
    }
}

// ================= launch =================
extern "C" void kernel_launch(void* const* d_in, const int* in_sizes, int n_in,
                              void* d_out, int out_size){
    const float* g    = (const float*)d_in[0];
    const float* query= (const float*)d_in[1];
    const float* qW   = (const float*)d_in[2];
    const float* qb   = (const float*)d_in[3];
    const float* kW   = (const float*)d_in[4];
    // d_in[5] = kb: cancels in softmax (constant over k)
    const float* gW1  = (const float*)d_in[6];
    const float* gb1  = (const float*)d_in[7];
    const float* gW2  = (const float*)d_in[8];
    const float* gb2  = (const float*)d_in[9];
    const float* gW3  = (const float*)d_in[10];
    const float* gb3  = (const float*)d_in[11];
    const float* pW1  = (const float*)d_in[12];
    const float* pb1  = (const float*)d_in[13];
    const float* pW2  = (const float*)d_in[14];
    const float* pb2  = (const float*)d_in[15];
    const float* pW3  = (const float*)d_in[16];
    const float* pb3  = (const float*)d_in[17];
    const float* tW   = (const float*)d_in[18];
    const float* tb   = (const float*)d_in[19];
    const float* wW   = (const float*)d_in[20];
    const float* wb   = (const float*)d_in[21];
    const float* cW   = (const float*)d_in[22];
    const float* cb   = (const float*)d_in[23];
    float* out = (float*)d_out;

    const int SMEM_MAIN = (2*NH*HS + 2*KT*NH + 64 + 64 + 192 + 192 + 256 + 256 + 64 + 132) * 4;
    cudaFuncSetAttribute(k_main, cudaFuncAttributeMaxDynamicSharedMemorySize, SMEM_MAIN);

    k_prep<<<1409, 512>>>(g, query, qW, qb, kW,
                          gW1, gb1, gW2, gb2, gW3, gb3,
                          pW1, pb1, pW2, pW3);
    k_main<<<dim3(NM/TM, NB), 512, SMEM_MAIN>>>(g, query, pW1, pb2, pb3,
                                                tW, tb, wW, wb, cW, cb, out);
}

// round 8
// speedup vs baseline: 9.8226x; 1.1364x over previous
#include <cuda_runtime.h>
#include <math.h>

#define NB 128
#define NK 64
#define NM 2048
#define NQD 128
#define NH 256
#define NC 32
#define HS 68      // padded row stride, float4-aligned, good bank spread
#define TM 64      // points per CTA
#define KT 16      // k-tile for weight staging

typedef unsigned long long ull;

// ---- scratch (no allocation allowed) ----
__device__ float d_inv[NB*NK];
__device__ float d_P[NB*NH];
__device__ float d_Qc[NM*NH];
__device__ float d_W2T[NH*NH];
__device__ float d_W3T[NH*NH];
__device__ float d_weff[NQD+1];

__device__ __forceinline__ float gelu_f(float x){
    return 0.5f*x*(1.0f + erff(x*0.7071067811865475f));
}
__device__ __forceinline__ float warp_red_sum(float v){
    v += __shfl_xor_sync(0xffffffffu, v, 16);
    v += __shfl_xor_sync(0xffffffffu, v, 8);
    v += __shfl_xor_sync(0xffffffffu, v, 4);
    v += __shfl_xor_sync(0xffffffffu, v, 2);
    v += __shfl_xor_sync(0xffffffffu, v, 1);
    return v;
}
__device__ __forceinline__ float warp_red_max(float v){
    v = fmaxf(v, __shfl_xor_sync(0xffffffffu, v, 16));
    v = fmaxf(v, __shfl_xor_sync(0xffffffffu, v, 8));
    v = fmaxf(v, __shfl_xor_sync(0xffffffffu, v, 4));
    v = fmaxf(v, __shfl_xor_sync(0xffffffffu, v, 2));
    v = fmaxf(v, __shfl_xor_sync(0xffffffffu, v, 1));
    return v;
}

// ---- f32x2 packed-FMA helpers (FFMA2 is PTX-only) ----
__device__ __forceinline__ ull pack2(float x, float y){
    ull r; asm("mov.b64 %0, {%1, %2};" : "=l"(r) : "f"(x), "f"(y)); return r;
}
__device__ __forceinline__ ull dup2(float x){
    ull r; asm("mov.b64 %0, {%1, %1};" : "=l"(r) : "f"(x)); return r;
}
__device__ __forceinline__ void fma2(ull& d, ull a, ull b){
    asm("fma.rn.f32x2 %0, %1, %2, %0;" : "+l"(d) : "l"(a), "l"(b));
}
__device__ __forceinline__ float2 unpack2(ull v){
    float2 f; asm("mov.b64 {%0, %1}, %2;" : "=f"(f.x), "=f"(f.y) : "l"(v)); return f;
}

// ================= unified prep kernel (roles by blockIdx.x) =================
__global__ void __launch_bounds__(512,1) k_prep(
    const float* __restrict__ g, const float* __restrict__ query,
    const float* __restrict__ qW, const float* __restrict__ qb,
    const float* __restrict__ kW,
    const float* __restrict__ gW1, const float* __restrict__ gb1,
    const float* __restrict__ gW2, const float* __restrict__ gb2,
    const float* __restrict__ gW3, const float* __restrict__ gb3,
    const float* __restrict__ pW1, const float* __restrict__ pb1,
    const float* __restrict__ pW2, const float* __restrict__ pW3)
{
    __shared__ float sb[1088];
    int blk = blockIdx.x, tid = threadIdx.x;

    if (blk < 128){
        int idx = blk*512 + tid;
        d_W2T[idx] = pW2[(idx & 255)*NH + (idx >> 8)];
    } else if (blk < 256){
        int idx = (blk-128)*512 + tid;
        d_W3T[idx] = pW3[(idx & 255)*NH + (idx >> 8)];
    } else if (blk < 384){
        int b = blk - 256;
        float* inv_s = sb;
        float* h1 = sb + 64;
        float* h2 = sb + 320;
        float* h3 = sb + 576;
        if (tid < NK){
            const float* gp = g + ((size_t)b*NK + tid)*3;
            float v = sqrtf(gp[0]*gp[0] + gp[1]*gp[1] + gp[2]*gp[2]);
            inv_s[tid] = v;
            d_inv[b*NK + tid] = v;
        }
        __syncthreads();
        if (tid < NH){
            float acc = gb1[tid];
            const float* wr = gW1 + tid*NK;
            #pragma unroll 8
            for (int k=0;k<NK;k++) acc += wr[k]*inv_s[k];
            h1[tid] = gelu_f(acc);
        }
        __syncthreads();
        if (tid < NH){
            float acc = gb2[tid];
            const float* wr = gW2 + tid*NH;
            #pragma unroll 8
            for (int k=0;k<NH;k++) acc += wr[k]*h1[k];
            h2[tid] = gelu_f(acc);
        }
        __syncthreads();
        if (tid < NH){
            float acc = gb3[tid];
            const float* wr = gW3 + tid*NH;
            #pragma unroll 8
            for (int k=0;k<NH;k++) acc += wr[k]*h2[k];
            h3[tid] = acc;
        }
        __syncthreads();
        if (tid < NH){
            float acc = pb1[tid];
            const float* wr = pW1 + (size_t)tid*385;
            #pragma unroll 8
            for (int k=0;k<NH;k++) acc += wr[k]*h3[k];
            d_P[b*NH + tid] = acc;
        }
    } else if (blk == 384){
        if (tid < NQD){
            float acc = 0.f;
            #pragma unroll 8
            for (int a=0;a<NQD;a++) acc += qW[a*NQD+tid]*kW[a];
            d_weff[tid] = acc;
        }
        if (tid == 128){
            float be = 0.f;
            for (int a=0;a<NQD;a++) be += qb[a]*kW[a];
            d_weff[NQD] = be;
        }
    } else {
        int bq = blk - 385;
        float* q_s = sb;
        if (tid < 256)
            q_s[tid] = query[((size_t)bq*2 + (tid>>7))*NQD + (tid & 127)];
        __syncthreads();
        int h = tid >> 8;
        int wv = (tid >> 5) & 7;
        int lid = tid & 31;
        int m = bq*2 + h;
        const float* qs = q_s + h*128;
        for (int it=0; it<32; it++){
            int j = it*8 + wv;
            const float* row = pW1 + (size_t)j*385 + NH;
            float acc = row[lid]      * qs[lid]
                      + row[lid+32]   * qs[lid+32]
                      + row[lid+64]   * qs[lid+64]
                      + row[lid+96]   * qs[lid+96];
            acc = warp_red_sum(acc);
            if (lid == 0) d_Qc[(size_t)m*NH + j] = acc;
        }
    }
}

// ================= GEMM layer: 64 pts x 256 outs x 256 k, 256 threads ========
// Warp w owns 8 points (rows), lane tx owns 8 cols {c*32+tx}.
// f32x2 accumulators: 4 row-pairs x 8 cols per thread = 64 FMAs / 32 FFMA2 per t.
template<bool GELU>
__device__ __forceinline__ void gemm_layer(const float* __restrict__ hIn,
        float* __restrict__ wt, const float* __restrict__ WT,
        const float* __restrict__ bias, float* __restrict__ hOut, int tid){
    const int tx = tid & 31;
    const int p0 = (tid >> 5) << 3;       // warp's 8 points
    ull acc[4][8];
    #pragma unroll
    for (int rp=0;rp<4;rp++)
        #pragma unroll
        for (int c=0;c<8;c++) acc[rp][c] = 0ull;

    {   // preload tile 0: 1024 float4 by 256 threads
        const float4* s = (const float4*)WT;
        float4* d = (float4*)wt;
        #pragma unroll
        for (int i=0;i<4;i++) d[tid + i*256] = s[tid + i*256];
    }
    __syncthreads();

    for (int kt=0; kt<NH/KT; kt++){
        float4 r[4];
        if (kt < NH/KT-1){
            const float4* s = (const float4*)(WT + (kt+1)*KT*NH);
            #pragma unroll
            for (int i=0;i<4;i++) r[i] = s[tid + i*256];
        }
        const float* buf = wt + (kt & 1)*(KT*NH);
        #pragma unroll
        for (int t=0;t<KT;t++){
            const float* arow = hIn + (kt*KT+t)*HS + p0;
            float4 a0 = *(const float4*)(arow);
            float4 a1 = *(const float4*)(arow+4);
            ull A[4] = {pack2(a0.x,a0.y), pack2(a0.z,a0.w),
                        pack2(a1.x,a1.y), pack2(a1.z,a1.w)};
            const float* brow = buf + t*NH + tx;
            #pragma unroll
            for (int c=0;c<8;c++){
                ull B = dup2(brow[c*32]);       // stride-1 across lanes
                #pragma unroll
                for (int rp=0;rp<4;rp++) fma2(acc[rp][c], A[rp], B);
            }
        }
        if (kt < NH/KT-1){
            float4* d = (float4*)(wt + ((kt+1) & 1)*(KT*NH));
            #pragma unroll
            for (int i=0;i<4;i++) d[tid + i*256] = r[i];
        }
        __syncthreads();
    }

    #pragma unroll
    for (int c=0;c<8;c++){
        int col = c*32 + tx;
        float bv = bias[col];
        float v[8];
        #pragma unroll
        for (int rp=0;rp<4;rp++){
            float2 f = unpack2(acc[rp][c]);
            v[rp*2]   = f.x + bv;
            v[rp*2+1] = f.y + bv;
        }
        if (GELU){
            #pragma unroll
            for (int i=0;i<8;i++) v[i] = gelu_f(v[i]);
        }
        *(float4*)(hOut + col*HS + p0)     = make_float4(v[0],v[1],v[2],v[3]);
        *(float4*)(hOut + col*HS + p0 + 4) = make_float4(v[4],v[5],v[6],v[7]);
    }
    __syncthreads();
}

// ================= fused main: 256 threads =================
__global__ void __launch_bounds__(256, 1)
k_main(const float* __restrict__ g, const float* __restrict__ query,
       const float* __restrict__ pW1,
       const float* __restrict__ pb2, const float* __restrict__ pb3,
       const float* __restrict__ tW, const float* __restrict__ tb,
       const float* __restrict__ wW, const float* __restrict__ wb,
       const float* __restrict__ cW, const float* __restrict__ cb,
       float* __restrict__ out){
    extern __shared__ float sm[];
    float* hA     = sm;                   // [256][HS]
    float* hB     = hA + NH*HS;           // [256][HS]  (also head-weight stage)
    float* wt     = hB + NH*HS;           // [2][KT*NH]
    float* inv_s  = wt + 2*KT*NH;         // 64
    float* ainv_s = inv_s + 64;           // 64
    float* y0_s   = ainv_s + 64;          // 192
    float* g_s    = y0_s + 192;           // 192
    float* P_s    = g_s + 192;            // 256
    float* w1c_s  = P_s + 256;            // 256
    float* c_s    = w1c_s + 256;          // 64
    float* weff_s = c_s + 64;             // 132

    int tid = threadIdx.x;
    int b = blockIdx.y;
    int m0 = blockIdx.x * TM;
    int lid = tid & 31, w = tid >> 5;     // 8 warps

    if (tid < 64)               inv_s[tid]  = d_inv[b*NK + tid];
    if (tid >= 64)              g_s[tid-64] = g[(size_t)b*NK*3 + (tid-64)];
    P_s[tid]   = d_P[b*NH + tid];
    w1c_s[tid] = pW1[(size_t)tid*385 + 384];
    if (tid < NQD+1) weff_s[tid] = d_weff[tid];
    __syncthreads();

    // ---- c[p]: 8 points per warp ----
    #pragma unroll
    for (int i=0;i<8;i++){
        int p = w*8 + i;
        const float* q = query + (size_t)(m0+p)*NQD;
        float acc = q[lid]      * weff_s[lid]
                  + q[lid+32]   * weff_s[lid+32]
                  + q[lid+64]   * weff_s[lid+64]
                  + q[lid+96]   * weff_s[lid+96];
        acc = warp_red_sum(acc);
        if (lid == 0) c_s[p] = (acc + weff_s[NQD]) * 0.08838834764831845f;
    }
    __syncthreads();

    // ---- attention: warp-cooperative softmax, 8 points per warp ----
    {
        float i1 = inv_s[lid], i2 = inv_s[lid+32];
        float gx0 = g_s[lid*3],      gx1 = g_s[lid*3+1],      gx2 = g_s[lid*3+2];
        float gy0 = g_s[(lid+32)*3], gy1 = g_s[(lid+32)*3+1], gy2 = g_s[(lid+32)*3+2];
        #pragma unroll
        for (int i=0;i<8;i++){
            int p = w*8 + i;
            float cm = c_s[p];
            float t1 = cm*i1, t2 = cm*i2;
            float mx = warp_red_max(fmaxf(t1, t2));
            float e1 = expf(t1 - mx), e2 = expf(t2 - mx);
            float s  = warp_red_sum(e1 + e2);
            float a0 = warp_red_sum(e1*gx0 + e2*gy0);
            float a1 = warp_red_sum(e1*gx1 + e2*gy1);
            float a2 = warp_red_sum(e1*gx2 + e2*gy2);
            float ai = warp_red_sum(e1*i1 + e2*i2);
            if (lid == 0){
                float r = 1.f/s;
                y0_s[p*3+0] = a0*r; y0_s[p*3+1] = a1*r; y0_s[p*3+2] = a2*r;
                ainv_s[p] = ai*r;
            }
        }
    }
    __syncthreads();

    // ---- layer 1 (separable): hA[j][p] = gelu(P[j] + Qc[m][j] + w1c[j]*ainv[p]) ----
    {
        float Pv = P_s[tid], wc = w1c_s[tid];
        const float* qc = d_Qc + (size_t)m0*NH + tid;     // coalesced across tid
        float* row = hA + tid*HS;
        for (int p=0;p<TM;p+=4){
            float4 v;
            v.x = gelu_f(Pv + qc[(size_t)(p+0)*NH] + wc*ainv_s[p+0]);
            v.y = gelu_f(Pv + qc[(size_t)(p+1)*NH] + wc*ainv_s[p+1]);
            v.z = gelu_f(Pv + qc[(size_t)(p+2)*NH] + wc*ainv_s[p+2]);
            v.w = gelu_f(Pv + qc[(size_t)(p+3)*NH] + wc*ainv_s[p+3]);
            *(float4*)(row + p) = v;
        }
    }
    __syncthreads();

    // ---- layer 2 + layer 3 ----
    gemm_layer<true >(hA, wt, d_W2T, pb2, hB, tid);
    gemm_layer<false>(hB, wt, d_W3T, pb3, hA, tid);    // s in hA[j][p]

    // ---- stage head weights into hB: hw[j*40 + o], o<34, j=tid ----
    #pragma unroll
    for (int o=0;o<34;o++){
        float v = (o < 32) ? tW[o*NH + tid] : ((o == 32) ? wW[tid] : cW[tid]);
        hB[tid*40 + o] = v;
    }
    __syncthreads();

    // ---- heads: lane owns point-pair (natural f32x2), warp owns 4 cols ----
    {
        int pp = lid*2;                   // points pp, pp+1
        ull acc[4] = {0ull,0ull,0ull,0ull};
        ull accx = 0ull;                  // extra head col (w<2 only)
        int cbase = w*4;
        int xcol = 32 + w;                // valid for w<2
        #pragma unroll 4
        for (int j=0;j<NH;j++){
            ull Ap = *(const ull*)(hA + j*HS + pp);       // lane-pair, conflict-free
            const float* hw = hB + j*40;
            #pragma unroll
            for (int c=0;c<4;c++){
                ull W = dup2(hw[cbase + c]);              // warp-broadcast
                fma2(acc[c], Ap, W);
            }
            if (w < 2){
                ull Wx = dup2(hw[xcol]);
                fma2(accx, Ap, Wx);
            }
        }
        size_t base = (size_t)b*NM + m0;
        float* outT = out + (size_t)NB*NM*3;
        #pragma unroll
        for (int c=0;c<4;c++){
            int col = cbase + c;
            float bv = tb[col];
            float2 f = unpack2(acc[c]);
            outT[(base + pp    )*NC + col] = f.x + bv;
            outT[(base + pp + 1)*NC + col] = f.y + bv;
        }
        if (w == 0){                      // weight-logit head
            float* outW = out + (size_t)NB*NM*3 + (size_t)NB*NM*NC;
            float2 f = unpack2(accx);
            outW[base + pp    ] = f.x + wb[0];
            outW[base + pp + 1] = f.y + wb[0];
        }
        if (w == 1){                      // gate head -> y outputs
            float2 f = unpack2(accx);
            float cbv = cb[0];
            #pragma unroll
            for (int i=0;i<2;i++){
                int p = pp + i;
                float gate = 1.f/(1.f + expf(-((i ? f.y : f.x) + cbv)));
                size_t pi = base + p;
                out[pi*3+0] = y0_s[p*3+0]*gate;
                out[pi*3+1] = y0_s[p*3+1]*gate;
                out[pi*3+2] = y0_s[p*3+2]*gate;
            }
        }
    }
}

// ================= launch =================
extern "C" void kernel_launch(void* const* d_in, const int* in_sizes, int n_in,
                              void* d_out, int out_size){
    const float* g    = (const float*)d_in[0];
    const float* query= (const float*)d_in[1];
    const float* qW   = (const float*)d_in[2];
    const float* qb   = (const float*)d_in[3];
    const float* kW   = (const float*)d_in[4];
    // d_in[5] = kb: cancels in softmax (constant over k)
    const float* gW1  = (const float*)d_in[6];
    const float* gb1  = (const float*)d_in[7];
    const float* gW2  = (const float*)d_in[8];
    const float* gb2  = (const float*)d_in[9];
    const float* gW3  = (const float*)d_in[10];
    const float* gb3  = (const float*)d_in[11];
    const float* pW1  = (const float*)d_in[12];
    const float* pb1  = (const float*)d_in[13];
    const float* pW2  = (const float*)d_in[14];
    const float* pb2  = (const float*)d_in[15];
    const float* pW3  = (const float*)d_in[16];
    const float* pb3  = (const float*)d_in[17];
    const float* tW   = (const float*)d_in[18];
    const float* tb   = (const float*)d_in[19];
    const float* wW   = (const float*)d_in[20];
    const float* wb   = (const float*)d_in[21];
    const float* cW   = (const float*)d_in[22];
    const float* cb   = (const float*)d_in[23];
    float* out = (float*)d_out;

    const int SMEM_MAIN = (2*NH*HS + 2*KT*NH + 64 + 64 + 192 + 192 + 256 + 256 + 64 + 132) * 4;
    cudaFuncSetAttribute(k_main, cudaFuncAttributeMaxDynamicSharedMemorySize, SMEM_MAIN);

    k_prep<<<1409, 512>>>(g, query, qW, qb, kW,
                          gW1, gb1, gW2, gb2, gW3, gb3,
                          pW1, pb1, pW2, pW3);
    k_main<<<dim3(NM/TM, NB), 256, SMEM_MAIN>>>(g, query, pW1, pb2, pb3,
                                                tW, tb, wW, wb, cW, cb, out);
}